// round 16
// baseline (speedup 1.0000x reference)
#include <cuda_runtime.h>
#include <cuda_bf16.h>
#include <cuda_fp16.h>
#include <math.h>
#include <stdint.h>

// B=32, S=1024, T=512, SRC=TGT=OUT=1024, H=8, dh=128
// R15: fused attention s-chunk 32 -> 64 (16 iters, LDSM:MMA 0.31, V rows 128B
//      with 8-way swizzle). Fixed-constant softmax, S packed to P per-ks.
//      GEMMs unchanged (R12-validated).

// ======================= helpers =======================
__device__ __forceinline__ uint32_t smem_u32(const void* p) {
    uint32_t a;
    asm("{ .reg .u64 t; cvta.to.shared.u64 t, %1; cvt.u32.u64 %0, t; }" : "=r"(a) : "l"(p));
    return a;
}

#define LDM4(d0, d1, d2, d3, addr)                                             \
    asm volatile("ldmatrix.sync.aligned.m8n8.x4.shared.b16 {%0,%1,%2,%3}, [%4];" \
                 : "=r"(d0), "=r"(d1), "=r"(d2), "=r"(d3) : "r"(addr))

#define MMA_HF(c, a, b)                                                        \
    asm volatile(                                                              \
        "mma.sync.aligned.m16n8k16.row.col.f32.f16.f16.f32 "                   \
        "{%0,%1,%2,%3},{%4,%5,%6,%7},{%8,%9},{%0,%1,%2,%3};"                   \
        : "+f"((c)[0]), "+f"((c)[1]), "+f"((c)[2]), "+f"((c)[3])               \
        : "r"((a)[0]), "r"((a)[1]), "r"((a)[2]), "r"((a)[3]),                  \
          "r"((b)[0]), "r"((b)[1]))

#define CPA(s, g) asm volatile("cp.async.cg.shared.global [%0], [%1], 16;" ::"r"(s), "l"(g))
#define CPCOMMIT() asm volatile("cp.async.commit_group;" ::: "memory")
#define CPWAIT0() asm volatile("cp.async.wait_group 0;" ::: "memory")
#define CPWAIT1() asm volatile("cp.async.wait_group 1;" ::: "memory")

__device__ __forceinline__ uint32_t packh(float a, float b) {
    __half2 h = __floats2half2_rn(a, b);
    return *reinterpret_cast<uint32_t*>(&h);
}

// ======================= scratch (static __device__) =======================
__device__ float d_scales[4];
__device__ float d_partial[3][256];

__device__ __nv_bfloat16 s_src_h[(size_t)32768 * 1024];
__device__ __nv_bfloat16 s_tgt_h[(size_t)16384 * 1024];
__device__ __nv_bfloat16 s_vsrc_h[(size_t)2048 * 1024];
__device__ __nv_bfloat16 s_vtgt_h[(size_t)1024 * 1024];
__device__ __nv_bfloat16 s_vout_h[(size_t)1024 * 2048];
__device__ __nv_bfloat16 s_key_h[(size_t)32768 * 1024];                  // K [b*s][d']
__device__ __nv_bfloat16 s_vsd_h[(size_t)32768 * 1024];                  // V [b*s][d']
__device__ __nv_bfloat16 s_vt_h[(size_t)32 * 1024 * 1024];               // V^T [b][d'][s]
__device__ __nv_bfloat16 s_q_h[(size_t)16384 * 1024];                    // Q [b*t][d']
__device__ __nv_bfloat16 s_tu_h[(size_t)16384 * 1024];                   // tu f16

// ======================= weight-norm scales =======================
__global__ void sumsq_partial(const float* __restrict__ v0, int n0,
                              const float* __restrict__ v1, int n1,
                              const float* __restrict__ v2, int n2) {
    int t = blockIdx.y;
    const float* v = (t == 0) ? v0 : (t == 1) ? v1 : v2;
    int n = (t == 0) ? n0 : (t == 1) ? n1 : n2;
    float s = 0.f;
    for (int i = blockIdx.x * blockDim.x + threadIdx.x; i < n; i += gridDim.x * blockDim.x) {
        float x = v[i];
        s += x * x;
    }
    __shared__ float sm[256];
    sm[threadIdx.x] = s;
    __syncthreads();
    for (int o = 128; o > 0; o >>= 1) {
        if (threadIdx.x < o) sm[threadIdx.x] += sm[threadIdx.x + o];
        __syncthreads();
    }
    if (threadIdx.x == 0) d_partial[t][blockIdx.x] = sm[0];
}

__global__ void finalize_scales(const float* __restrict__ g0,
                                const float* __restrict__ g1,
                                const float* __restrict__ g2) {
    int t = blockIdx.x;
    __shared__ float sm[256];
    sm[threadIdx.x] = d_partial[t][threadIdx.x];
    __syncthreads();
    for (int o = 128; o > 0; o >>= 1) {
        if (threadIdx.x < o) sm[threadIdx.x] += sm[threadIdx.x + o];
        __syncthreads();
    }
    if (threadIdx.x == 0) {
        float g = (t == 0) ? *g0 : (t == 1) ? *g1 : *g2;
        d_scales[t] = g / sqrtf(sm[0]);
    }
}

// ======================= merged fp32 -> f16 splits (5 regions, 1 launch) =======================
__global__ void split_all(const float* __restrict__ i0, __nv_bfloat16* __restrict__ o0, int n0,
                          const float* __restrict__ i1, __nv_bfloat16* __restrict__ o1, int n1,
                          const float* __restrict__ i2, __nv_bfloat16* __restrict__ o2, int n2,
                          const float* __restrict__ i3, __nv_bfloat16* __restrict__ o3, int n3,
                          const float* __restrict__ i4, __nv_bfloat16* __restrict__ o4, int n4) {
    int reg = blockIdx.y;
    const float4* ip;
    uint2* op;
    int n;  // in float4 units
    switch (reg) {
        case 0: ip = (const float4*)i0; op = (uint2*)o0; n = n0; break;
        case 1: ip = (const float4*)i1; op = (uint2*)o1; n = n1; break;
        case 2: ip = (const float4*)i2; op = (uint2*)o2; n = n2; break;
        case 3: ip = (const float4*)i3; op = (uint2*)o3; n = n3; break;
        default: ip = (const float4*)i4; op = (uint2*)o4; n = n4; break;
    }
    for (int c = blockIdx.x * blockDim.x + threadIdx.x; c < n; c += gridDim.x * blockDim.x) {
        float4 v = ip[c];
        op[c] = make_uint2(packh(v.x, v.y), packh(v.z, v.w));
    }
}

// ======================= V transpose (2-byte): out[b][c][s] = in[b*1024+s][c] ==========
__global__ void transposeV(const __nv_bfloat16* __restrict__ in, __nv_bfloat16* __restrict__ out) {
    __shared__ __nv_bfloat16 t[64][66];
    int b = blockIdx.z;
    int s0 = blockIdx.x * 64, c0 = blockIdx.y * 64;
    int tx = threadIdx.x;
    for (int r = threadIdx.y; r < 64; r += 8) {
        uint32_t v = *(const uint32_t*)(in + ((size_t)(b * 1024 + s0 + r)) * 1024 + c0 + tx * 2);
        *(uint32_t*)&t[r][tx * 2] = v;
    }
    __syncthreads();
    for (int r = threadIdx.y; r < 64; r += 8) {
        uint32_t p = (*(uint16_t*)&t[tx * 2][r]) | ((uint32_t)(*(uint16_t*)&t[tx * 2 + 1][r]) << 16);
        *(uint32_t*)(out + ((size_t)b << 20) + (size_t)(c0 + r) * 1024 + s0 + tx * 2) = p;
    }
}

// ======================= HMMA fp16 GEMM: 4 warps, 64x64 warp tile (R12 validated) ==========
#define G_STG 32768
#define G_OBH 16384

__device__ __forceinline__ void load_mat_async128(const __nv_bfloat16* __restrict__ G,
                                                  int ld, int rb, int k0,
                                                  uint32_t sdst, int tid) {
#pragma unroll
    for (int p = 0; p < 8; p++) {
        int idx = tid + p * 128;
        int row = idx >> 3, ch = idx & 7;
        CPA(sdst + (uint32_t)(row * 128 + ((ch ^ (row & 7)) << 4)),
            G + (size_t)(rb + row) * ld + k0 + ch * 8);
    }
}

__global__ void __launch_bounds__(128, 2)
mma_gemm(const __nv_bfloat16* __restrict__ Ahi, const __nv_bfloat16* __restrict__ A2hi,
         const __nv_bfloat16* __restrict__ Bhi,
         float* __restrict__ Cf,
         __nv_bfloat16* __restrict__ Ch0, __nv_bfloat16* __restrict__ Ch1,
         int splitN, int ldcb,
         const float* __restrict__ bias, const float* __restrict__ mask,
         float scaleMul, int scaleIdx,
         int K, int splitK, int lda, int lda2, int ldb, int ldc) {
    extern __shared__ char smem[];
    uint32_t sb = smem_u32(smem);
    int tid = threadIdx.x;
    int wid = tid >> 5, lane = tid & 31;

    int rowBase = blockIdx.y * 128;
    int colBase = blockIdx.x * 128;
    int wm = wid & 1, wn = wid >> 1;

    float acc[4][8][4];
#pragma unroll
    for (int i = 0; i < 4; i++)
#pragma unroll
        for (int j = 0; j < 8; j++)
#pragma unroll
            for (int q = 0; q < 4; q++) acc[i][j][q] = 0.f;

    uint32_t aTerm[4];
    int aSw[4];
    int aK = lane >> 4;
#pragma unroll
    for (int f = 0; f < 4; f++) {
        int r = wm * 64 + f * 16 + (lane & 15);
        aTerm[f] = (uint32_t)(r * 128);
        aSw[f] = r & 7;
    }
    uint32_t bTerm[4];
    int bSw[4];
    int bK = (lane >> 3) & 1;
#pragma unroll
    for (int nb = 0; nb < 4; nb++) {
        int r = wn * 64 + nb * 16 + (lane & 7) + ((lane >> 4) << 3);
        bTerm[nb] = (uint32_t)(r * 128);
        bSw[nb] = r & 7;
    }

    int nIter = K >> 6;

    load_mat_async128(Ahi, lda, rowBase, 0, sb, tid);
    load_mat_async128(Bhi, ldb, colBase, 0, sb + G_OBH, tid);
    CPCOMMIT();
    {
        const __nv_bfloat16* ah = Ahi;
        int la = lda, kk = 64;
        if (A2hi && 64 >= splitK) { ah = A2hi; la = lda2; kk = 64 - splitK; }
        load_mat_async128(ah, la, rowBase, kk, sb + G_STG, tid);
        load_mat_async128(Bhi, ldb, colBase, 64, sb + G_STG + G_OBH, tid);
        CPCOMMIT();
    }

    int stage = 0;
    for (int it = 0; it < nIter; it++) {
        CPWAIT1();
        __syncthreads();
        if (it + 2 < nIter) {
            int k0 = (it + 2) << 6;
            const __nv_bfloat16* ah = Ahi;
            int la = lda, kk = k0;
            if (A2hi && k0 >= splitK) { ah = A2hi; la = lda2; kk = k0 - splitK; }
            int ps = stage + 2;
            if (ps >= 3) ps -= 3;
            uint32_t sB = sb + ps * G_STG;
            load_mat_async128(ah, la, rowBase, kk, sB, tid);
            load_mat_async128(Bhi, ldb, colBase, k0, sB + G_OBH, tid);
        }
        CPCOMMIT();
        uint32_t base = sb + stage * G_STG;
#pragma unroll
        for (int ks = 0; ks < 4; ks++) {
            uint32_t ah[4][4], bh[8][2];
            int kcA = ks * 2 + aK;
            int kcB = ks * 2 + bK;
#pragma unroll
            for (int f = 0; f < 4; f++) {
                uint32_t addr = base + aTerm[f] + (uint32_t)((kcA ^ aSw[f]) << 4);
                LDM4(ah[f][0], ah[f][1], ah[f][2], ah[f][3], addr);
            }
#pragma unroll
            for (int nb = 0; nb < 4; nb++) {
                uint32_t addr = base + G_OBH + bTerm[nb] + (uint32_t)((kcB ^ bSw[nb]) << 4);
                LDM4(bh[nb * 2][0], bh[nb * 2][1], bh[nb * 2 + 1][0], bh[nb * 2 + 1][1], addr);
            }
#pragma unroll
            for (int mi = 0; mi < 4; mi++)
#pragma unroll
                for (int nj = 0; nj < 8; nj++)
                    MMA_HF(acc[mi][nj], ah[mi], bh[nj]);
        }
        if (++stage == 3) stage = 0;
    }

    float s = scaleMul * (scaleIdx >= 0 ? d_scales[scaleIdx] : 1.0f);
    int r0 = rowBase + wm * 64 + (lane >> 2);
    int c0 = colBase + wn * 64 + (lane & 3) * 2;
#pragma unroll
    for (int nj = 0; nj < 8; nj++) {
        int c = c0 + nj * 8;
        float b0 = 0.f, b1 = 0.f;
        if (bias) { b0 = bias[c]; b1 = bias[c + 1]; }
#pragma unroll
        for (int mi = 0; mi < 4; mi++) {
            int r = r0 + mi * 16;
            float v0 = acc[mi][nj][0] * s + b0;
            float v1 = acc[mi][nj][1] * s + b1;
            float v2 = acc[mi][nj][2] * s + b0;
            float v3 = acc[mi][nj][3] * s + b1;
            if (mask) {
                float m0 = mask[r];
                float m8 = mask[r + 8];
                v0 *= m0; v1 *= m0; v2 *= m8; v3 *= m8;
            }
            if (Cf) {
                *(float2*)(Cf + (size_t)r * ldc + c) = make_float2(v0, v1);
                *(float2*)(Cf + (size_t)(r + 8) * ldc + c) = make_float2(v2, v3);
            } else {
                __nv_bfloat16* H = Ch0;
                int cc = c;
                if (splitN && cc >= splitN) { H = Ch1; cc -= splitN; }
                *(uint32_t*)(H + (size_t)r * ldcb + cc) = packh(v0, v1);
                *(uint32_t*)(H + (size_t)(r + 8) * ldcb + cc) = packh(v2, v3);
            }
        }
    }
}

// ======================= flash-fused attention: 4 warps x 32 rows, s-chunk 64 ==========
// SMEM: Q 32KB | 2 stages x (K 16KB + V 16KB + mask 256B). 2 CTAs/SM.
// K tile: 64 rows x 256B (8-swizzle). V^T tile: 128 rows x 128B (8-swizzle).
#define FA_STAGE0 32768
#define FA_STRIDE 33024
#define FA_VOFF 16384
#define FA_MOFF 32768
#define FA_SMEM (32768 + 2 * 33024)

__global__ void __launch_bounds__(128, 2)
fused_attn(const __nv_bfloat16* __restrict__ qh, const __nv_bfloat16* __restrict__ kh,
           const __nv_bfloat16* __restrict__ vth, const float* __restrict__ mask,
           __nv_bfloat16* __restrict__ oh) {
    extern __shared__ char smem[];
    uint32_t sb = smem_u32(smem);
    int tid = threadIdx.x, wid = tid >> 5, lane = tid & 31;
    int tile = blockIdx.x;
    int b = blockIdx.y >> 3, h = blockIdx.y & 7;
    int g = lane >> 2, t4 = lane & 3;

    size_t qrow0 = (size_t)(b * 512 + tile * 128);

    // Q tile (128 x 128 f16, 32KB) via cp.async
#pragma unroll
    for (int i = 0; i < 16; i++) {
        int idx = tid + i * 128;
        int r = idx >> 4, ch = idx & 15;
        CPA(sb + (uint32_t)(r * 256 + ((ch ^ (r & 7)) << 4)),
            qh + (qrow0 + r) * 1024 + h * 128 + ch * 8);
    }

    // geometry: warp owns rows wid*32 .. wid*32+31 (two 16-row mi-groups)
    uint32_t qRow[2];
    int qSw[2];
#pragma unroll
    for (int mi = 0; mi < 2; mi++) {
        int r = wid * 32 + mi * 16 + (lane & 15);
        qRow[mi] = (uint32_t)(r * 256);
        qSw[mi] = r & 7;
    }
    int aK = lane >> 4;
    int bK = (lane >> 3) & 1;
    int nr = (lane & 7) + ((lane >> 4) << 3);
    uint32_t kT0 = (uint32_t)(nr * 256);   // K: 256B rows
    int kSw = nr & 7;
    uint32_t vT0 = (uint32_t)(nr * 128);   // V^T: 128B rows
    int vSw = nr & 7;

    float O[2][16][4];
#pragma unroll
    for (int mi = 0; mi < 2; mi++)
#pragma unroll
        for (int f = 0; f < 16; f++) {
            O[mi][f][0] = O[mi][f][1] = O[mi][f][2] = O[mi][f][3] = 0.f;
        }
    float l00 = 0.f, l01 = 0.f, l10 = 0.f, l11 = 0.f;

    auto load_chunk = [&](int c0, int st) {
        uint32_t base = sb + FA_STAGE0 + st * FA_STRIDE;
        // K: 64 rows x 16 chunks of 16B
#pragma unroll
        for (int i = 0; i < 8; i++) {
            int idx = tid + i * 128;
            int r = idx >> 4, ch = idx & 15;
            CPA(base + (uint32_t)(r * 256 + ((ch ^ (r & 7)) << 4)),
                kh + ((size_t)(b * 1024 + c0 + r)) * 1024 + h * 128 + ch * 8);
        }
        // V^T: 128 rows x 8 chunks of 16B
#pragma unroll
        for (int i = 0; i < 8; i++) {
            int idx = tid + i * 128;
            int r = idx >> 3, ch = idx & 7;
            CPA(base + FA_VOFF + (uint32_t)(r * 128 + ((ch ^ (r & 7)) << 4)),
                vth + ((size_t)b << 20) + (size_t)(h * 128 + r) * 1024 + c0 + ch * 8);
        }
        if (tid < 16)
            CPA(base + FA_MOFF + tid * 16, mask + b * 1024 + c0 + tid * 4);
    };

    load_chunk(0, 0);
    CPCOMMIT();

    const float scq = 0.08838834764831845f;

    for (int it = 0; it < 16; it++) {
        CPWAIT0();
        __syncthreads();
        if (it + 1 < 16) { load_chunk((it + 1) * 64, (it + 1) & 1); CPCOMMIT(); }
        uint32_t st = sb + FA_STAGE0 + (it & 1) * FA_STRIDE;

        float S[2][8][4];
#pragma unroll
        for (int mi = 0; mi < 2; mi++)
#pragma unroll
            for (int j = 0; j < 8; j++) {
                S[mi][j][0] = S[mi][j][1] = S[mi][j][2] = S[mi][j][3] = 0.f;
            }

        // ---- QK: K frag shared across mi ----
#pragma unroll
        for (int kc = 0; kc < 8; kc++) {
            uint32_t A0[4], A1[4];
            LDM4(A0[0], A0[1], A0[2], A0[3],
                 sb + qRow[0] + (uint32_t)((((kc << 1) + aK) ^ qSw[0]) << 4));
            LDM4(A1[0], A1[1], A1[2], A1[3],
                 sb + qRow[1] + (uint32_t)((((kc << 1) + aK) ^ qSw[1]) << 4));
#pragma unroll
            for (int nb = 0; nb < 4; nb++) {
                uint32_t Bv[4];
                LDM4(Bv[0], Bv[1], Bv[2], Bv[3],
                     st + kT0 + (uint32_t)(nb * 4096) +
                         (uint32_t)((((kc << 1) + bK) ^ kSw) << 4));
                MMA_HF(S[0][nb * 2], A0, Bv);
                MMA_HF(S[0][nb * 2 + 1], A0, Bv + 2);
                MMA_HF(S[1][nb * 2], A1, Bv);
                MMA_HF(S[1][nb * 2 + 1], A1, Bv + 2);
            }
        }

        // ---- fixed-constant softmax numerator + pack to P (S dies per-ks) ----
        float* mk = (float*)(smem + FA_STAGE0 + (it & 1) * FA_STRIDE + FA_MOFF);
        uint32_t P[2][4][4];
#pragma unroll
        for (int j = 0; j < 8; j++) {
            float ma = mk[j * 8 + 2 * t4], mb2 = mk[j * 8 + 2 * t4 + 1];
            S[0][j][0] = __expf(S[0][j][0] * scq) * ma;
            S[0][j][1] = __expf(S[0][j][1] * scq) * mb2;
            S[0][j][2] = __expf(S[0][j][2] * scq) * ma;
            S[0][j][3] = __expf(S[0][j][3] * scq) * mb2;
            S[1][j][0] = __expf(S[1][j][0] * scq) * ma;
            S[1][j][1] = __expf(S[1][j][1] * scq) * mb2;
            S[1][j][2] = __expf(S[1][j][2] * scq) * ma;
            S[1][j][3] = __expf(S[1][j][3] * scq) * mb2;
            l00 += S[0][j][0] + S[0][j][1];
            l01 += S[0][j][2] + S[0][j][3];
            l10 += S[1][j][0] + S[1][j][1];
            l11 += S[1][j][2] + S[1][j][3];
        }
#pragma unroll
        for (int ks = 0; ks < 4; ks++) {
#pragma unroll
            for (int mi = 0; mi < 2; mi++) {
                P[mi][ks][0] = packh(S[mi][2 * ks][0], S[mi][2 * ks][1]);
                P[mi][ks][1] = packh(S[mi][2 * ks][2], S[mi][2 * ks][3]);
                P[mi][ks][2] = packh(S[mi][2 * ks + 1][0], S[mi][2 * ks + 1][1]);
                P[mi][ks][3] = packh(S[mi][2 * ks + 1][2], S[mi][2 * ks + 1][3]);
            }
        }

        // ---- PV: V frag shared across mi ----
#pragma unroll
        for (int ks = 0; ks < 4; ks++) {
#pragma unroll
            for (int db = 0; db < 8; db++) {
                uint32_t Vv[4];
                LDM4(Vv[0], Vv[1], Vv[2], Vv[3],
                     st + FA_VOFF + (uint32_t)(db * 2048) + vT0 +
                         (uint32_t)((((ks << 1) + bK) ^ vSw) << 4));
                MMA_HF(O[0][db * 2], P[0][ks], Vv);
                MMA_HF(O[0][db * 2 + 1], P[0][ks], Vv + 2);
                MMA_HF(O[1][db * 2], P[1][ks], Vv);
                MMA_HF(O[1][db * 2 + 1], P[1][ks], Vv + 2);
            }
        }
    }

    // ---- end-of-loop l reduction across the 4 lanes of each row ----
    l00 += __shfl_xor_sync(0xffffffffu, l00, 1);
    l00 += __shfl_xor_sync(0xffffffffu, l00, 2);
    l01 += __shfl_xor_sync(0xffffffffu, l01, 1);
    l01 += __shfl_xor_sync(0xffffffffu, l01, 2);
    l10 += __shfl_xor_sync(0xffffffffu, l10, 1);
    l10 += __shfl_xor_sync(0xffffffffu, l10, 2);
    l11 += __shfl_xor_sync(0xffffffffu, l11, 1);
    l11 += __shfl_xor_sync(0xffffffffu, l11, 2);

    float inv0[2] = {1.f / l00, 1.f / l10};
    float inv1[2] = {1.f / l01, 1.f / l11};
#pragma unroll
    for (int mi = 0; mi < 2; mi++) {
        size_t row0 = (qrow0 + wid * 32 + mi * 16 + g) * 1024;
        float i0 = inv0[mi], i1 = inv1[mi];
#pragma unroll
        for (int f = 0; f < 16; f++) {
            int c = h * 128 + f * 8 + 2 * t4;
            *(uint32_t*)(oh + row0 + c) = packh(O[mi][f][0] * i0, O[mi][f][1] * i0);
            *(uint32_t*)(oh + row0 + 8 * 1024 + c) = packh(O[mi][f][2] * i1, O[mi][f][3] * i1);
        }
    }
}

// ======================= launch =======================
extern "C" void kernel_launch(void* const* d_in, const int* in_sizes, int n_in,
                              void* d_out, int out_size) {
    const float* src = (const float*)d_in[0];
    const float* tgt = (const float*)d_in[1];
    const float* src_mask = (const float*)d_in[2];
    const float* tgt_mask = (const float*)d_in[3];
    const float* v_src = (const float*)d_in[4];
    const float* g_src = (const float*)d_in[5];
    const float* b_src = (const float*)d_in[6];
    const float* v_tgt = (const float*)d_in[7];
    const float* g_tgt = (const float*)d_in[8];
    const float* b_tgt = (const float*)d_in[9];
    const float* v_out = (const float*)d_in[10];
    const float* g_out = (const float*)d_in[11];
    const float* b_out = (const float*)d_in[12];
    float* out = (float*)d_out;

    cudaFuncSetAttribute(mma_gemm, cudaFuncAttributeMaxDynamicSharedMemorySize, 98304);
    cudaFuncSetAttribute(fused_attn, cudaFuncAttributeMaxDynamicSharedMemorySize, FA_SMEM);

#define SYM(T, p, s) T* p; { void* q; cudaGetSymbolAddress(&q, s); p = (T*)q; }
    SYM(__nv_bfloat16, srch, s_src_h)
    SYM(__nv_bfloat16, tgth, s_tgt_h)
    SYM(__nv_bfloat16, vsh, s_vsrc_h)
    SYM(__nv_bfloat16, vth, s_vtgt_h)
    SYM(__nv_bfloat16, voh, s_vout_h)
    SYM(__nv_bfloat16, kh, s_key_h)
    SYM(__nv_bfloat16, vsdh, s_vsd_h)
    SYM(__nv_bfloat16, vvh, s_vt_h)
    SYM(__nv_bfloat16, qh, s_q_h)
    SYM(__nv_bfloat16, tuh, s_tu_h)
#undef SYM

    // weight-norm scales
    sumsq_partial<<<dim3(256, 3), 256>>>(v_src, 2048 * 1024, v_tgt, 1024 * 1024, v_out, 1024 * 2048);
    finalize_scales<<<3, 256>>>(g_src, g_tgt, g_out);

    // all input/weight splits in ONE launch (float4 counts)
    split_all<<<dim3(256, 5), 256>>>(
        src, srch, 32768 * 256,
        tgt, tgth, 16384 * 256,
        v_src, vsh, 2048 * 256,
        v_tgt, vth, 1024 * 256,
        v_out, voh, 1024 * 512);

    // GEMM1: K | V f16 = rowmask*(src @ (s0*v_src)^T + b_src)
    mma_gemm<<<dim3(16, 256, 1), 128, 98304>>>(
        srch, nullptr, vsh, nullptr,
        kh, vsdh, 1024, 1024,
        b_src, src_mask, 1.0f, 0,
        1024, 0, 1024, 0, 1024, 0);

    // V transpose
    transposeV<<<dim3(16, 16, 32), dim3(32, 8)>>>(vsdh, vvh);

    // GEMM2: Q f16 = rowmask*(tgt @ (s1*v_tgt)^T + b_tgt)
    mma_gemm<<<dim3(8, 128, 1), 128, 98304>>>(
        tgth, nullptr, vth, nullptr,
        qh, nullptr, 0, 1024,
        b_tgt, tgt_mask, 1.0f, 1,
        1024, 0, 1024, 0, 1024, 0);

    // flash-fused attention -> tu f16
    fused_attn<<<dim3(4, 256), 128, FA_SMEM>>>(qh, kh, vvh, src_mask, tuh);

    // GEMM3: out fp32 = [tgt | tu] @ (s2*v_out)^T + b_out
    mma_gemm<<<dim3(8, 128, 1), 128, 98304>>>(
        tgth, tuh, voh, out,
        nullptr, nullptr, 0, 0,
        b_out, nullptr, 1.0f, 2,
        2048, 1024, 1024, 1024, 2048, 1024);
}

// round 17
// speedup vs baseline: 1.0099x; 1.0099x over previous
#include <cuda_runtime.h>
#include <cuda_bf16.h>
#include <cuda_fp16.h>
#include <math.h>
#include <stdint.h>

// B=32, S=1024, T=512, SRC=TGT=OUT=1024, H=8, dh=128
// R16: R14 attention (chunk 32, 4 warps x 32 rows, shared K/V frags, fixed-const
//      softmax) upgraded to a 3-stage cp.async pipeline (wait_group 1).
//      GEMMs unchanged (R12-validated).

// ======================= helpers =======================
__device__ __forceinline__ uint32_t smem_u32(const void* p) {
    uint32_t a;
    asm("{ .reg .u64 t; cvta.to.shared.u64 t, %1; cvt.u32.u64 %0, t; }" : "=r"(a) : "l"(p));
    return a;
}

#define LDM4(d0, d1, d2, d3, addr)                                             \
    asm volatile("ldmatrix.sync.aligned.m8n8.x4.shared.b16 {%0,%1,%2,%3}, [%4];" \
                 : "=r"(d0), "=r"(d1), "=r"(d2), "=r"(d3) : "r"(addr))

#define MMA_HF(c, a, b)                                                        \
    asm volatile(                                                              \
        "mma.sync.aligned.m16n8k16.row.col.f32.f16.f16.f32 "                   \
        "{%0,%1,%2,%3},{%4,%5,%6,%7},{%8,%9},{%0,%1,%2,%3};"                   \
        : "+f"((c)[0]), "+f"((c)[1]), "+f"((c)[2]), "+f"((c)[3])               \
        : "r"((a)[0]), "r"((a)[1]), "r"((a)[2]), "r"((a)[3]),                  \
          "r"((b)[0]), "r"((b)[1]))

#define CPA(s, g) asm volatile("cp.async.cg.shared.global [%0], [%1], 16;" ::"r"(s), "l"(g))
#define CPCOMMIT() asm volatile("cp.async.commit_group;" ::: "memory")
#define CPWAIT0() asm volatile("cp.async.wait_group 0;" ::: "memory")
#define CPWAIT1() asm volatile("cp.async.wait_group 1;" ::: "memory")

__device__ __forceinline__ uint32_t packh(float a, float b) {
    __half2 h = __floats2half2_rn(a, b);
    return *reinterpret_cast<uint32_t*>(&h);
}

// ======================= scratch (static __device__) =======================
__device__ float d_scales[4];
__device__ float d_partial[3][256];

__device__ __nv_bfloat16 s_src_h[(size_t)32768 * 1024];
__device__ __nv_bfloat16 s_tgt_h[(size_t)16384 * 1024];
__device__ __nv_bfloat16 s_vsrc_h[(size_t)2048 * 1024];
__device__ __nv_bfloat16 s_vtgt_h[(size_t)1024 * 1024];
__device__ __nv_bfloat16 s_vout_h[(size_t)1024 * 2048];
__device__ __nv_bfloat16 s_key_h[(size_t)32768 * 1024];                  // K [b*s][d']
__device__ __nv_bfloat16 s_vsd_h[(size_t)32768 * 1024];                  // V [b*s][d']
__device__ __nv_bfloat16 s_vt_h[(size_t)32 * 1024 * 1024];               // V^T [b][d'][s]
__device__ __nv_bfloat16 s_q_h[(size_t)16384 * 1024];                    // Q [b*t][d']
__device__ __nv_bfloat16 s_tu_h[(size_t)16384 * 1024];                   // tu f16

// ======================= weight-norm scales =======================
__global__ void sumsq_partial(const float* __restrict__ v0, int n0,
                              const float* __restrict__ v1, int n1,
                              const float* __restrict__ v2, int n2) {
    int t = blockIdx.y;
    const float* v = (t == 0) ? v0 : (t == 1) ? v1 : v2;
    int n = (t == 0) ? n0 : (t == 1) ? n1 : n2;
    float s = 0.f;
    for (int i = blockIdx.x * blockDim.x + threadIdx.x; i < n; i += gridDim.x * blockDim.x) {
        float x = v[i];
        s += x * x;
    }
    __shared__ float sm[256];
    sm[threadIdx.x] = s;
    __syncthreads();
    for (int o = 128; o > 0; o >>= 1) {
        if (threadIdx.x < o) sm[threadIdx.x] += sm[threadIdx.x + o];
        __syncthreads();
    }
    if (threadIdx.x == 0) d_partial[t][blockIdx.x] = sm[0];
}

__global__ void finalize_scales(const float* __restrict__ g0,
                                const float* __restrict__ g1,
                                const float* __restrict__ g2) {
    int t = blockIdx.x;
    __shared__ float sm[256];
    sm[threadIdx.x] = d_partial[t][threadIdx.x];
    __syncthreads();
    for (int o = 128; o > 0; o >>= 1) {
        if (threadIdx.x < o) sm[threadIdx.x] += sm[threadIdx.x + o];
        __syncthreads();
    }
    if (threadIdx.x == 0) {
        float g = (t == 0) ? *g0 : (t == 1) ? *g1 : *g2;
        d_scales[t] = g / sqrtf(sm[0]);
    }
}

// ======================= merged fp32 -> f16 splits (5 regions, 1 launch) =======================
__global__ void split_all(const float* __restrict__ i0, __nv_bfloat16* __restrict__ o0, int n0,
                          const float* __restrict__ i1, __nv_bfloat16* __restrict__ o1, int n1,
                          const float* __restrict__ i2, __nv_bfloat16* __restrict__ o2, int n2,
                          const float* __restrict__ i3, __nv_bfloat16* __restrict__ o3, int n3,
                          const float* __restrict__ i4, __nv_bfloat16* __restrict__ o4, int n4) {
    int reg = blockIdx.y;
    const float4* ip;
    uint2* op;
    int n;  // in float4 units
    switch (reg) {
        case 0: ip = (const float4*)i0; op = (uint2*)o0; n = n0; break;
        case 1: ip = (const float4*)i1; op = (uint2*)o1; n = n1; break;
        case 2: ip = (const float4*)i2; op = (uint2*)o2; n = n2; break;
        case 3: ip = (const float4*)i3; op = (uint2*)o3; n = n3; break;
        default: ip = (const float4*)i4; op = (uint2*)o4; n = n4; break;
    }
    for (int c = blockIdx.x * blockDim.x + threadIdx.x; c < n; c += gridDim.x * blockDim.x) {
        float4 v = ip[c];
        op[c] = make_uint2(packh(v.x, v.y), packh(v.z, v.w));
    }
}

// ======================= V transpose (2-byte): out[b][c][s] = in[b*1024+s][c] ==========
__global__ void transposeV(const __nv_bfloat16* __restrict__ in, __nv_bfloat16* __restrict__ out) {
    __shared__ __nv_bfloat16 t[64][66];
    int b = blockIdx.z;
    int s0 = blockIdx.x * 64, c0 = blockIdx.y * 64;
    int tx = threadIdx.x;
    for (int r = threadIdx.y; r < 64; r += 8) {
        uint32_t v = *(const uint32_t*)(in + ((size_t)(b * 1024 + s0 + r)) * 1024 + c0 + tx * 2);
        *(uint32_t*)&t[r][tx * 2] = v;
    }
    __syncthreads();
    for (int r = threadIdx.y; r < 64; r += 8) {
        uint32_t p = (*(uint16_t*)&t[tx * 2][r]) | ((uint32_t)(*(uint16_t*)&t[tx * 2 + 1][r]) << 16);
        *(uint32_t*)(out + ((size_t)b << 20) + (size_t)(c0 + r) * 1024 + s0 + tx * 2) = p;
    }
}

// ======================= HMMA fp16 GEMM: 4 warps, 64x64 warp tile (R12 validated) ==========
#define G_STG 32768
#define G_OBH 16384

__device__ __forceinline__ void load_mat_async128(const __nv_bfloat16* __restrict__ G,
                                                  int ld, int rb, int k0,
                                                  uint32_t sdst, int tid) {
#pragma unroll
    for (int p = 0; p < 8; p++) {
        int idx = tid + p * 128;
        int row = idx >> 3, ch = idx & 7;
        CPA(sdst + (uint32_t)(row * 128 + ((ch ^ (row & 7)) << 4)),
            G + (size_t)(rb + row) * ld + k0 + ch * 8);
    }
}

__global__ void __launch_bounds__(128, 2)
mma_gemm(const __nv_bfloat16* __restrict__ Ahi, const __nv_bfloat16* __restrict__ A2hi,
         const __nv_bfloat16* __restrict__ Bhi,
         float* __restrict__ Cf,
         __nv_bfloat16* __restrict__ Ch0, __nv_bfloat16* __restrict__ Ch1,
         int splitN, int ldcb,
         const float* __restrict__ bias, const float* __restrict__ mask,
         float scaleMul, int scaleIdx,
         int K, int splitK, int lda, int lda2, int ldb, int ldc) {
    extern __shared__ char smem[];
    uint32_t sb = smem_u32(smem);
    int tid = threadIdx.x;
    int wid = tid >> 5, lane = tid & 31;

    int rowBase = blockIdx.y * 128;
    int colBase = blockIdx.x * 128;
    int wm = wid & 1, wn = wid >> 1;

    float acc[4][8][4];
#pragma unroll
    for (int i = 0; i < 4; i++)
#pragma unroll
        for (int j = 0; j < 8; j++)
#pragma unroll
            for (int q = 0; q < 4; q++) acc[i][j][q] = 0.f;

    uint32_t aTerm[4];
    int aSw[4];
    int aK = lane >> 4;
#pragma unroll
    for (int f = 0; f < 4; f++) {
        int r = wm * 64 + f * 16 + (lane & 15);
        aTerm[f] = (uint32_t)(r * 128);
        aSw[f] = r & 7;
    }
    uint32_t bTerm[4];
    int bSw[4];
    int bK = (lane >> 3) & 1;
#pragma unroll
    for (int nb = 0; nb < 4; nb++) {
        int r = wn * 64 + nb * 16 + (lane & 7) + ((lane >> 4) << 3);
        bTerm[nb] = (uint32_t)(r * 128);
        bSw[nb] = r & 7;
    }

    int nIter = K >> 6;

    load_mat_async128(Ahi, lda, rowBase, 0, sb, tid);
    load_mat_async128(Bhi, ldb, colBase, 0, sb + G_OBH, tid);
    CPCOMMIT();
    {
        const __nv_bfloat16* ah = Ahi;
        int la = lda, kk = 64;
        if (A2hi && 64 >= splitK) { ah = A2hi; la = lda2; kk = 64 - splitK; }
        load_mat_async128(ah, la, rowBase, kk, sb + G_STG, tid);
        load_mat_async128(Bhi, ldb, colBase, 64, sb + G_STG + G_OBH, tid);
        CPCOMMIT();
    }

    int stage = 0;
    for (int it = 0; it < nIter; it++) {
        CPWAIT1();
        __syncthreads();
        if (it + 2 < nIter) {
            int k0 = (it + 2) << 6;
            const __nv_bfloat16* ah = Ahi;
            int la = lda, kk = k0;
            if (A2hi && k0 >= splitK) { ah = A2hi; la = lda2; kk = k0 - splitK; }
            int ps = stage + 2;
            if (ps >= 3) ps -= 3;
            uint32_t sB = sb + ps * G_STG;
            load_mat_async128(ah, la, rowBase, kk, sB, tid);
            load_mat_async128(Bhi, ldb, colBase, k0, sB + G_OBH, tid);
        }
        CPCOMMIT();
        uint32_t base = sb + stage * G_STG;
#pragma unroll
        for (int ks = 0; ks < 4; ks++) {
            uint32_t ah[4][4], bh[8][2];
            int kcA = ks * 2 + aK;
            int kcB = ks * 2 + bK;
#pragma unroll
            for (int f = 0; f < 4; f++) {
                uint32_t addr = base + aTerm[f] + (uint32_t)((kcA ^ aSw[f]) << 4);
                LDM4(ah[f][0], ah[f][1], ah[f][2], ah[f][3], addr);
            }
#pragma unroll
            for (int nb = 0; nb < 4; nb++) {
                uint32_t addr = base + G_OBH + bTerm[nb] + (uint32_t)((kcB ^ bSw[nb]) << 4);
                LDM4(bh[nb * 2][0], bh[nb * 2][1], bh[nb * 2 + 1][0], bh[nb * 2 + 1][1], addr);
            }
#pragma unroll
            for (int mi = 0; mi < 4; mi++)
#pragma unroll
                for (int nj = 0; nj < 8; nj++)
                    MMA_HF(acc[mi][nj], ah[mi], bh[nj]);
        }
        if (++stage == 3) stage = 0;
    }

    float s = scaleMul * (scaleIdx >= 0 ? d_scales[scaleIdx] : 1.0f);
    int r0 = rowBase + wm * 64 + (lane >> 2);
    int c0 = colBase + wn * 64 + (lane & 3) * 2;
#pragma unroll
    for (int nj = 0; nj < 8; nj++) {
        int c = c0 + nj * 8;
        float b0 = 0.f, b1 = 0.f;
        if (bias) { b0 = bias[c]; b1 = bias[c + 1]; }
#pragma unroll
        for (int mi = 0; mi < 4; mi++) {
            int r = r0 + mi * 16;
            float v0 = acc[mi][nj][0] * s + b0;
            float v1 = acc[mi][nj][1] * s + b1;
            float v2 = acc[mi][nj][2] * s + b0;
            float v3 = acc[mi][nj][3] * s + b1;
            if (mask) {
                float m0 = mask[r];
                float m8 = mask[r + 8];
                v0 *= m0; v1 *= m0; v2 *= m8; v3 *= m8;
            }
            if (Cf) {
                *(float2*)(Cf + (size_t)r * ldc + c) = make_float2(v0, v1);
                *(float2*)(Cf + (size_t)(r + 8) * ldc + c) = make_float2(v2, v3);
            } else {
                __nv_bfloat16* H = Ch0;
                int cc = c;
                if (splitN && cc >= splitN) { H = Ch1; cc -= splitN; }
                *(uint32_t*)(H + (size_t)r * ldcb + cc) = packh(v0, v1);
                *(uint32_t*)(H + (size_t)(r + 8) * ldcb + cc) = packh(v2, v3);
            }
        }
    }
}

// ======================= flash-fused attention: 4 warps x 32 rows, chunk 32, 3-stage ====
// SMEM: Q 32KB | 3 stages x (K 8KB + V 8KB + mask 128B + pad) = 82304 B. 2 CTAs/SM.
#define FA_STAGE0 32768
#define FA_STRIDE 16512
#define FA_VOFF 8192
#define FA_MOFF 16384
#define FA_SMEM (32768 + 3 * 16512)

__global__ void __launch_bounds__(128, 2)
fused_attn(const __nv_bfloat16* __restrict__ qh, const __nv_bfloat16* __restrict__ kh,
           const __nv_bfloat16* __restrict__ vth, const float* __restrict__ mask,
           __nv_bfloat16* __restrict__ oh) {
    extern __shared__ char smem[];
    uint32_t sb = smem_u32(smem);
    int tid = threadIdx.x, wid = tid >> 5, lane = tid & 31;
    int tile = blockIdx.x;
    int b = blockIdx.y >> 3, h = blockIdx.y & 7;
    int g = lane >> 2, t4 = lane & 3;

    size_t qrow0 = (size_t)(b * 512 + tile * 128);

    // Q tile (128 x 128 f16, 32KB) via cp.async
#pragma unroll
    for (int i = 0; i < 16; i++) {
        int idx = tid + i * 128;
        int r = idx >> 4, ch = idx & 15;
        CPA(sb + (uint32_t)(r * 256 + ((ch ^ (r & 7)) << 4)),
            qh + (qrow0 + r) * 1024 + h * 128 + ch * 8);
    }

    // geometry: warp owns rows wid*32 .. wid*32+31 (two 16-row mi-groups)
    uint32_t qRow[2];
    int qSw[2];
#pragma unroll
    for (int mi = 0; mi < 2; mi++) {
        int r = wid * 32 + mi * 16 + (lane & 15);
        qRow[mi] = (uint32_t)(r * 256);
        qSw[mi] = r & 7;
    }
    int aK = lane >> 4;
    int bK = (lane >> 3) & 1;
    int nr = (lane & 7) + ((lane >> 4) << 3);
    uint32_t kT0 = (uint32_t)(nr * 256);
    int kSw = nr & 7;
    uint32_t vT0 = (uint32_t)(nr * 64);
    int vSw = nr & 3;

    float O[2][16][4];
#pragma unroll
    for (int mi = 0; mi < 2; mi++)
#pragma unroll
        for (int f = 0; f < 16; f++) {
            O[mi][f][0] = O[mi][f][1] = O[mi][f][2] = O[mi][f][3] = 0.f;
        }
    float l00 = 0.f, l01 = 0.f, l10 = 0.f, l11 = 0.f;

    auto load_chunk = [&](int c0, int st) {
        uint32_t base = sb + FA_STAGE0 + st * FA_STRIDE;
#pragma unroll
        for (int i = 0; i < 4; i++) {
            int idx = tid + i * 128;
            int r = idx >> 4, ch = idx & 15;
            CPA(base + (uint32_t)(r * 256 + ((ch ^ (r & 7)) << 4)),
                kh + ((size_t)(b * 1024 + c0 + r)) * 1024 + h * 128 + ch * 8);
        }
#pragma unroll
        for (int i = 0; i < 4; i++) {
            int idx = tid + i * 128;
            int r = idx >> 2, ch = idx & 3;
            CPA(base + FA_VOFF + (uint32_t)(r * 64 + ((ch ^ (r & 3)) << 4)),
                vth + ((size_t)b << 20) + (size_t)(h * 128 + r) * 1024 + c0 + ch * 8);
        }
        if (tid < 8)
            CPA(base + FA_MOFF + tid * 16, mask + b * 1024 + c0 + tid * 4);
    };

    // prologue: stages 0 and 1 (Q rides with stage-0 group)
    load_chunk(0, 0);
    CPCOMMIT();
    load_chunk(32, 1);
    CPCOMMIT();

    const float scq = 0.08838834764831845f;

    int stage = 0;
    for (int it = 0; it < 32; it++) {
        CPWAIT1();
        __syncthreads();
        if (it + 2 < 32) {
            int ps = stage + 2;
            if (ps >= 3) ps -= 3;
            load_chunk((it + 2) * 32, ps);
        }
        CPCOMMIT();  // unconditional: uniform pending-group count
        uint32_t st = sb + FA_STAGE0 + stage * FA_STRIDE;

        float S[2][4][4];
#pragma unroll
        for (int mi = 0; mi < 2; mi++)
#pragma unroll
            for (int j = 0; j < 4; j++) {
                S[mi][j][0] = S[mi][j][1] = S[mi][j][2] = S[mi][j][3] = 0.f;
            }

        // ---- QK: K frag shared across mi ----
#pragma unroll
        for (int kc = 0; kc < 8; kc++) {
            uint32_t A0[4], A1[4];
            LDM4(A0[0], A0[1], A0[2], A0[3],
                 sb + qRow[0] + (uint32_t)((((kc << 1) + aK) ^ qSw[0]) << 4));
            LDM4(A1[0], A1[1], A1[2], A1[3],
                 sb + qRow[1] + (uint32_t)((((kc << 1) + aK) ^ qSw[1]) << 4));
#pragma unroll
            for (int nb = 0; nb < 2; nb++) {
                uint32_t Bv[4];
                LDM4(Bv[0], Bv[1], Bv[2], Bv[3],
                     st + kT0 + (uint32_t)(nb * 4096) +
                         (uint32_t)((((kc << 1) + bK) ^ kSw) << 4));
                MMA_HF(S[0][nb * 2], A0, Bv);
                MMA_HF(S[0][nb * 2 + 1], A0, Bv + 2);
                MMA_HF(S[1][nb * 2], A1, Bv);
                MMA_HF(S[1][nb * 2 + 1], A1, Bv + 2);
            }
        }

        // ---- fixed-constant softmax numerator: P = exp(s)*mask ----
        float* mk = (float*)(smem + FA_STAGE0 + stage * FA_STRIDE + FA_MOFF);
#pragma unroll
        for (int j = 0; j < 4; j++) {
            float ma = mk[j * 8 + 2 * t4], mb2 = mk[j * 8 + 2 * t4 + 1];
            S[0][j][0] = __expf(S[0][j][0] * scq) * ma;
            S[0][j][1] = __expf(S[0][j][1] * scq) * mb2;
            S[0][j][2] = __expf(S[0][j][2] * scq) * ma;
            S[0][j][3] = __expf(S[0][j][3] * scq) * mb2;
            S[1][j][0] = __expf(S[1][j][0] * scq) * ma;
            S[1][j][1] = __expf(S[1][j][1] * scq) * mb2;
            S[1][j][2] = __expf(S[1][j][2] * scq) * ma;
            S[1][j][3] = __expf(S[1][j][3] * scq) * mb2;
            l00 += S[0][j][0] + S[0][j][1];
            l01 += S[0][j][2] + S[0][j][3];
            l10 += S[1][j][0] + S[1][j][1];
            l11 += S[1][j][2] + S[1][j][3];
        }

        // ---- PV: V frag shared across mi ----
#pragma unroll
        for (int ks = 0; ks < 2; ks++) {
            uint32_t P0[4], P1[4];
            P0[0] = packh(S[0][2 * ks][0], S[0][2 * ks][1]);
            P0[1] = packh(S[0][2 * ks][2], S[0][2 * ks][3]);
            P0[2] = packh(S[0][2 * ks + 1][0], S[0][2 * ks + 1][1]);
            P0[3] = packh(S[0][2 * ks + 1][2], S[0][2 * ks + 1][3]);
            P1[0] = packh(S[1][2 * ks][0], S[1][2 * ks][1]);
            P1[1] = packh(S[1][2 * ks][2], S[1][2 * ks][3]);
            P1[2] = packh(S[1][2 * ks + 1][0], S[1][2 * ks + 1][1]);
            P1[3] = packh(S[1][2 * ks + 1][2], S[1][2 * ks + 1][3]);
#pragma unroll
            for (int db = 0; db < 8; db++) {
                uint32_t Vv[4];
                LDM4(Vv[0], Vv[1], Vv[2], Vv[3],
                     st + FA_VOFF + (uint32_t)(db * 1024) + vT0 +
                         (uint32_t)((((ks << 1) + bK) ^ vSw) << 4));
                MMA_HF(O[0][db * 2], P0, Vv);
                MMA_HF(O[0][db * 2 + 1], P0, Vv + 2);
                MMA_HF(O[1][db * 2], P1, Vv);
                MMA_HF(O[1][db * 2 + 1], P1, Vv + 2);
            }
        }
        if (++stage == 3) stage = 0;
    }

    // ---- end-of-loop l reduction across the 4 lanes of each row ----
    l00 += __shfl_xor_sync(0xffffffffu, l00, 1);
    l00 += __shfl_xor_sync(0xffffffffu, l00, 2);
    l01 += __shfl_xor_sync(0xffffffffu, l01, 1);
    l01 += __shfl_xor_sync(0xffffffffu, l01, 2);
    l10 += __shfl_xor_sync(0xffffffffu, l10, 1);
    l10 += __shfl_xor_sync(0xffffffffu, l10, 2);
    l11 += __shfl_xor_sync(0xffffffffu, l11, 1);
    l11 += __shfl_xor_sync(0xffffffffu, l11, 2);

    float inv0[2] = {1.f / l00, 1.f / l10};
    float inv1[2] = {1.f / l01, 1.f / l11};
#pragma unroll
    for (int mi = 0; mi < 2; mi++) {
        size_t row0 = (qrow0 + wid * 32 + mi * 16 + g) * 1024;
        float i0 = inv0[mi], i1 = inv1[mi];
#pragma unroll
        for (int f = 0; f < 16; f++) {
            int c = h * 128 + f * 8 + 2 * t4;
            *(uint32_t*)(oh + row0 + c) = packh(O[mi][f][0] * i0, O[mi][f][1] * i0);
            *(uint32_t*)(oh + row0 + 8 * 1024 + c) = packh(O[mi][f][2] * i1, O[mi][f][3] * i1);
        }
    }
}

// ======================= launch =======================
extern "C" void kernel_launch(void* const* d_in, const int* in_sizes, int n_in,
                              void* d_out, int out_size) {
    const float* src = (const float*)d_in[0];
    const float* tgt = (const float*)d_in[1];
    const float* src_mask = (const float*)d_in[2];
    const float* tgt_mask = (const float*)d_in[3];
    const float* v_src = (const float*)d_in[4];
    const float* g_src = (const float*)d_in[5];
    const float* b_src = (const float*)d_in[6];
    const float* v_tgt = (const float*)d_in[7];
    const float* g_tgt = (const float*)d_in[8];
    const float* b_tgt = (const float*)d_in[9];
    const float* v_out = (const float*)d_in[10];
    const float* g_out = (const float*)d_in[11];
    const float* b_out = (const float*)d_in[12];
    float* out = (float*)d_out;

    cudaFuncSetAttribute(mma_gemm, cudaFuncAttributeMaxDynamicSharedMemorySize, 98304);
    cudaFuncSetAttribute(fused_attn, cudaFuncAttributeMaxDynamicSharedMemorySize, FA_SMEM);

#define SYM(T, p, s) T* p; { void* q; cudaGetSymbolAddress(&q, s); p = (T*)q; }
    SYM(__nv_bfloat16, srch, s_src_h)
    SYM(__nv_bfloat16, tgth, s_tgt_h)
    SYM(__nv_bfloat16, vsh, s_vsrc_h)
    SYM(__nv_bfloat16, vth, s_vtgt_h)
    SYM(__nv_bfloat16, voh, s_vout_h)
    SYM(__nv_bfloat16, kh, s_key_h)
    SYM(__nv_bfloat16, vsdh, s_vsd_h)
    SYM(__nv_bfloat16, vvh, s_vt_h)
    SYM(__nv_bfloat16, qh, s_q_h)
    SYM(__nv_bfloat16, tuh, s_tu_h)
#undef SYM

    // weight-norm scales
    sumsq_partial<<<dim3(256, 3), 256>>>(v_src, 2048 * 1024, v_tgt, 1024 * 1024, v_out, 1024 * 2048);
    finalize_scales<<<3, 256>>>(g_src, g_tgt, g_out);

    // all input/weight splits in ONE launch (float4 counts)
    split_all<<<dim3(256, 5), 256>>>(
        src, srch, 32768 * 256,
        tgt, tgth, 16384 * 256,
        v_src, vsh, 2048 * 256,
        v_tgt, vth, 1024 * 256,
        v_out, voh, 1024 * 512);

    // GEMM1: K | V f16 = rowmask*(src @ (s0*v_src)^T + b_src)
    mma_gemm<<<dim3(16, 256, 1), 128, 98304>>>(
        srch, nullptr, vsh, nullptr,
        kh, vsdh, 1024, 1024,
        b_src, src_mask, 1.0f, 0,
        1024, 0, 1024, 0, 1024, 0);

    // V transpose
    transposeV<<<dim3(16, 16, 32), dim3(32, 8)>>>(vsdh, vvh);

    // GEMM2: Q f16 = rowmask*(tgt @ (s1*v_tgt)^T + b_tgt)
    mma_gemm<<<dim3(8, 128, 1), 128, 98304>>>(
        tgth, nullptr, vth, nullptr,
        qh, nullptr, 0, 1024,
        b_tgt, tgt_mask, 1.0f, 1,
        1024, 0, 1024, 0, 1024, 0);

    // flash-fused attention -> tu f16
    fused_attn<<<dim3(4, 256), 128, FA_SMEM>>>(qh, kh, vvh, src_mask, tuh);

    // GEMM3: out fp32 = [tgt | tu] @ (s2*v_out)^T + b_out
    mma_gemm<<<dim3(8, 128, 1), 128, 98304>>>(
        tgth, tuh, voh, out,
        nullptr, nullptr, 0, 0,
        b_out, nullptr, 1.0f, 2,
        2048, 1024, 1024, 1024, 2048, 1024);
}